// round 11
// baseline (speedup 1.0000x reference)
#include <cuda_runtime.h>

#define B  64
#define C  512
#define S  768
#define K  128
#define KN 256
#define A  200
#define H  1024

#define NBLK 256
#define NTHR 256
#define KSPLIT 16
#define SCHUNK (S / KSPLIT)   // 48

// Scratch (device globals — no allocation allowed)
__device__ float g_xmp[4 * B * S];        // x-sum partials (4 c-quarters) [cq][b][s]
__device__ float g_fcp[KSPLIT * H * B];   // fc partials [ks][h][b]

// Grid-wide sense-reversing barrier (single atomic counter — measured faster
// than distributed flag polling (R7) and ticket stealing (R9)).
__device__ int          g_bar_count = 0;
__device__ volatile int g_bar_sense = 0;

__device__ __forceinline__ void grid_barrier(int& ls) {
    __syncthreads();
    if (threadIdx.x == 0) {
        const int target = ls ^ 1;
        ls = target;
        __threadfence();
        if (atomicAdd(&g_bar_count, 1) == NBLK - 1) {
            atomicExch(&g_bar_count, 0);
            __threadfence();
            g_bar_sense = target;
        } else {
            while (g_bar_sense != target) { }
        }
        __threadfence();
    } else {
        ls ^= 1;
    }
    __syncthreads();
}

__device__ __forceinline__ void f4add(float4& a, const float4 v) {
    a.x += v.x; a.y += v.y; a.z += v.z; a.w += v.w;
}

// ---- cache-policy load/store helpers --------------------------------------
// .nc variants: ONLY for pure kernel inputs (R4: .nc on same-kernel-written
// data reads stale). L1::no_allocate keeps zero-reuse streams out of L1.
__device__ __forceinline__ float4 ldg_stream(const float4* p) {     // input, v4
    float4 v;
    asm volatile("ld.global.nc.L1::no_allocate.L2::256B.v4.f32 {%0,%1,%2,%3}, [%4];"
                 : "=f"(v.x), "=f"(v.y), "=f"(v.z), "=f"(v.w)
                 : "l"(p));
    return v;
}
__device__ __forceinline__ float ldg_stream_f(const float* p) {     // input, f32
    float v;
    asm("ld.global.nc.L1::no_allocate.L2::256B.f32 %0, [%1];" : "=f"(v) : "l"(p));
    return v;
}
__device__ __forceinline__ float ld_na_f(const float* p) {          // coherent
    float v;
    asm("ld.global.L1::no_allocate.f32 %0, [%1];" : "=f"(v) : "l"(p));
    return v;
}
__device__ __forceinline__ float4 ld_na_f4(const float4* p) {       // coherent
    float4 v;
    asm("ld.global.L1::no_allocate.v4.f32 {%0,%1,%2,%3}, [%4];"
        : "=f"(v.x), "=f"(v.y), "=f"(v.z), "=f"(v.w) : "l"(p));
    return v;
}
__device__ __forceinline__ void st_na_f4(float4* p, float4 v) {
    asm volatile("st.global.L1::no_allocate.v4.f32 [%0], {%1,%2,%3,%4};"
                 :: "l"(p), "f"(v.x), "f"(v.y), "f"(v.z), "f"(v.w) : "memory");
}
__device__ __forceinline__ void st_na_f(float* p, float v) {
    asm volatile("st.global.L1::no_allocate.f32 [%0], %1;"
                 :: "l"(p), "f"(v) : "memory");
}

__global__ void __launch_bounds__(NTHR, 2)
ham_persistent(const float* __restrict__ x,
               const float* __restrict__ W_t,
               const float* __restrict__ b_t,
               const float* __restrict__ gamma,
               const float* __restrict__ beta,
               const float* __restrict__ W_l,
               const float* __restrict__ b_l,
               const float* __restrict__ G_h,
               float* __restrict__ out_score,
               float* __restrict__ out_fc,
               float* __restrict__ out_omega) {
    __shared__ __align__(16) float sm[4352];   // 17.4 KB, reused per phase

    const int blk = blockIdx.x;
    const int tid = threadIdx.x;
    int ls = g_bar_sense;                      // replay-safe sense init

    // ---------------- Phase 1: x-sum partials (unchanged from R10) ---------
    {
        const int cq  = blk >> 6;              // 0..3
        const int b   = blk & 63;
        const int cs  = tid >> 6;              // 0..3
        const int s64 = tid & 63;

        const float4* p = reinterpret_cast<const float4*>(x)
                        + ((size_t)b * C + cq * 128 + cs * 32) * (S / 4);
        float4 a0 = make_float4(0.f, 0.f, 0.f, 0.f);
        float4 a1 = a0, a2 = a0;
#pragma unroll 8
        for (int c = 0; c < 32; ++c) {
            const float4* row = p + c * (S / 4);
            f4add(a0, ldg_stream(row + s64));
            f4add(a1, ldg_stream(row + s64 + 64));
            f4add(a2, ldg_stream(row + s64 + 128));
        }
        float4* sm4 = reinterpret_cast<float4*>(sm);   // [4][192]
        sm4[cs * 192 + s64]       = a0;
        sm4[cs * 192 + s64 + 64]  = a1;
        sm4[cs * 192 + s64 + 128] = a2;
        __syncthreads();
        if (tid < 192) {
            float4 r = sm4[tid];
            f4add(r, sm4[192 + tid]);
            f4add(r, sm4[384 + tid]);
            f4add(r, sm4[576 + tid]);
            st_na_f4(reinterpret_cast<float4*>(g_xmp) + (cq * B + b) * (S / 4) + tid, r);
        }
    }
    grid_barrier(ls);

    // ---------------- Phase 2: fc partial GEMM -----------------------------
    // fc[b,h] = sum_s x_mean[b,s] * (W_t[h,s] + 4*W_t[h,s+S]); x_mean built
    // on the fly from the 4 c-quarter partials (L2-resident).
    // 256 blocks = 16 h-tiles x 16 s-splits of 48; 4x4 register tile.
    {
        float (*Xs)[64] = reinterpret_cast<float(*)[64]>(sm);          // [sk][b]
        float (*Ws)[64] = reinterpret_cast<float(*)[64]>(sm + 1024);   // [sk][h]
        const int h0 = (blk >> 4) * 64;
        const int s0 = (blk & 15) * SCHUNK;
        const int tx = tid & 15;          // b group
        const int ty = tid >> 4;          // h group

        float acc[4][4] = {};             // [h][b]
        for (int sc = 0; sc < SCHUNK; sc += 16) {
            for (int i = tid; i < 1024; i += NTHR) {
                int hh = i >> 4, sk = i & 15;
                int s = s0 + sc + sk;
                const float* wr = W_t + (size_t)(h0 + hh) * (2 * S);
                Ws[sk][hh] = ldg_stream_f(wr + s) + 4.0f * ldg_stream_f(wr + s + S);
            }
            for (int i = tid; i < 1024; i += NTHR) {
                int bb = i >> 4, sk = i & 15;
                int idx = bb * S + s0 + sc + sk;
                float v = ld_na_f(g_xmp + idx)
                        + ld_na_f(g_xmp + B * S + idx)
                        + ld_na_f(g_xmp + 2 * B * S + idx)
                        + ld_na_f(g_xmp + 3 * B * S + idx);
                Xs[sk][bb] = v * (1.0f / C);
            }
            __syncthreads();
#pragma unroll
            for (int sk = 0; sk < 16; ++sk) {
                float a_[4], w_[4];
#pragma unroll
                for (int i = 0; i < 4; ++i) a_[i] = Ws[sk][ty * 4 + i];
#pragma unroll
                for (int j = 0; j < 4; ++j) w_[j] = Xs[sk][tx * 4 + j];
#pragma unroll
                for (int i = 0; i < 4; ++i)
#pragma unroll
                    for (int j = 0; j < 4; ++j)
                        acc[i][j] += a_[i] * w_[j];
            }
            __syncthreads();
        }
        float* dst = g_fcp + (size_t)(blk & 15) * (H * B);
#pragma unroll
        for (int i = 0; i < 4; ++i) {
            float4 v = make_float4(acc[i][0], acc[i][1], acc[i][2], acc[i][3]);
            st_na_f4(reinterpret_cast<float4*>(&dst[(h0 + ty * 4 + i) * B + tx * 4]), v);
        }
    }
    grid_barrier(ls);

    // ---------------- Phase 3: BN (biased var over batch) + ReLU -----------
    // block handles 4 h columns x all 64 b; writes out_fc [b][h].
    {
        const int b    = tid & 63;
        const int hl   = tid >> 6;
        const int h    = blk * 4 + hl;
        const int wid  = tid >> 5;
        const int lane = tid & 31;

        float v = b_t[h];
#pragma unroll
        for (int ks = 0; ks < KSPLIT; ++ks)
            v += ld_na_f(g_fcp + (size_t)ks * (H * B) + h * B + b);

        float s = v;
#pragma unroll
        for (int o = 16; o; o >>= 1) s += __shfl_down_sync(0xffffffffu, s, o);
        if (!lane) sm[wid] = s;
        __syncthreads();
        const float mean = (sm[hl * 2] + sm[hl * 2 + 1]) * (1.0f / B);

        const float d = v - mean;
        float s2 = d * d;
#pragma unroll
        for (int o = 16; o; o >>= 1) s2 += __shfl_down_sync(0xffffffffu, s2, o);
        if (!lane) sm[8 + wid] = s2;
        __syncthreads();
        const float var = (sm[8 + hl * 2] + sm[8 + hl * 2 + 1]) * (1.0f / B);

        st_na_f(out_fc + b * H + h,
                fmaxf(d * rsqrtf(var + 1e-5f) * gamma[h] + beta[h], 0.0f));
    }
    grid_barrier(ls);

    // ---------------- Phase 4: score = sigmoid(relu_fc @ W_l^T + b_l) ------
    // block = (b-quad, k-octet): 16 x 16 = 256 blocks. W_l rows reused by 4 b.
    {
        const int b0 = (blk >> 4) * 4;
        const int k0 = (blk & 15) * 8;
        float4* r4 = reinterpret_cast<float4*>(sm);     // [4][256] float4

        for (int i = tid; i < 4 * (H / 4); i += NTHR)
            r4[i] = ld_na_f4(reinterpret_cast<const float4*>(out_fc)
                        + (b0 + (i >> 8)) * (H / 4) + (i & 255));
        __syncthreads();

        const int w = tid >> 5, lane = tid & 31;
        const int k = k0 + w;
        const float4* wl4 = reinterpret_cast<const float4*>(W_l + (size_t)k * H);
        float acc0 = 0.f, acc1 = 0.f, acc2 = 0.f, acc3 = 0.f;
#pragma unroll
        for (int j = 0; j < 8; ++j) {
            const float4 wv = __ldg(wl4 + lane + 32 * j);
            const float4 a0 = r4[0 * 256 + lane + 32 * j];
            const float4 a1 = r4[1 * 256 + lane + 32 * j];
            const float4 a2 = r4[2 * 256 + lane + 32 * j];
            const float4 a3 = r4[3 * 256 + lane + 32 * j];
            acc0 += a0.x * wv.x + a0.y * wv.y + a0.z * wv.z + a0.w * wv.w;
            acc1 += a1.x * wv.x + a1.y * wv.y + a1.z * wv.z + a1.w * wv.w;
            acc2 += a2.x * wv.x + a2.y * wv.y + a2.z * wv.z + a2.w * wv.w;
            acc3 += a3.x * wv.x + a3.y * wv.y + a3.z * wv.z + a3.w * wv.w;
        }
#pragma unroll
        for (int o = 16; o; o >>= 1) {
            acc0 += __shfl_down_sync(0xffffffffu, acc0, o);
            acc1 += __shfl_down_sync(0xffffffffu, acc1, o);
            acc2 += __shfl_down_sync(0xffffffffu, acc2, o);
            acc3 += __shfl_down_sync(0xffffffffu, acc3, o);
        }
        if (!lane) {
            const float bl = b_l[k];
            out_score[(b0 + 0) * K + k] = 1.0f / (1.0f + expf(-(acc0 + bl)));
            out_score[(b0 + 1) * K + k] = 1.0f / (1.0f + expf(-(acc1 + bl)));
            out_score[(b0 + 2) * K + k] = 1.0f / (1.0f + expf(-(acc2 + bl)));
            out_score[(b0 + 3) * K + k] = 1.0f / (1.0f + expf(-(acc3 + bl)));
        }
    }
    grid_barrier(ls);

    // ---------------- Phase 5: Q = score @ G_h, omega broadcast ------------
    // block = (b, n-slice of 64): 64 x 4 = 256 blocks.
    {
        const int b  = blk >> 2;
        const int n0 = (blk & 3) * 64;
        float* scsh  = sm;          // [128] score
        float* qpart = sm + 128;    // [4][64]
        float* qv    = sm + 384;    // [64]

        if (tid < K) scsh[tid] = out_score[b * K + tid];  // plain load (ours)
        __syncthreads();

        const int kh = tid >> 6;    // 0..3 -> k range [kh*32, kh*32+32)
        const int n  = tid & 63;
        float acc = 0.f;
#pragma unroll 8
        for (int j = 0; j < 32; ++j) {
            const int k = kh * 32 + j;
            acc += scsh[k] * __ldg(G_h + k * KN + n0 + n);
        }
        qpart[kh * 64 + n] = acc;
        __syncthreads();
        if (tid < 64)
            qv[tid] = qpart[tid] + qpart[64 + tid]
                    + qpart[128 + tid] + qpart[192 + tid];
        __syncthreads();

        // write 64 n rows x 200 a = 3200 float4
        float4* po = reinterpret_cast<float4*>(
            out_omega + (size_t)b * KN * A + (size_t)n0 * A);
#pragma unroll
        for (int it = 0; it < 13; ++it) {
            const int i4 = it * NTHR + tid;
            if (i4 < 64 * (A / 4)) {
                const float v = qv[i4 / (A / 4)];
                st_na_f4(po + i4, make_float4(v, v, v, v));
            }
        }
    }
}

// ---------------------------------------------------------------------------
extern "C" void kernel_launch(void* const* d_in, const int* in_sizes, int n_in,
                              void* d_out, int out_size) {
    const float* x     = (const float*)d_in[0];
    // d_in[1] omega_h, d_in[2] W_s1, d_in[3] W_s2: mathematically dead
    const float* W_t   = (const float*)d_in[4];
    const float* b_t   = (const float*)d_in[5];
    const float* gamma = (const float*)d_in[6];
    const float* beta  = (const float*)d_in[7];
    const float* W_l   = (const float*)d_in[8];
    const float* b_l   = (const float*)d_in[9];
    const float* G_h   = (const float*)d_in[10];

    float* out       = (float*)d_out;
    float* out_score = out;                    // [B, K]
    float* out_fc    = out + B * K;            // [B, H]
    float* out_omega = out + B * K + B * H;    // [B, KN, A]

    ham_persistent<<<NBLK, NTHR>>>(x, W_t, b_t, gamma, beta, W_l, b_l, G_h,
                                   out_score, out_fc, out_omega);
}

// round 12
// speedup vs baseline: 1.0963x; 1.0963x over previous
#include <cuda_runtime.h>

#define B  64
#define C  512
#define S  768
#define K  128
#define KN 256
#define A  200
#define H  1024

#define NBLK 256
#define NTHR 256
#define KSPLIT 16
#define SCHUNK (S / KSPLIT)   // 48

// Scratch (device globals — no allocation allowed)
__device__ float g_xmp[4 * B * S];        // x-sum partials (4 c-quarters) [cq][b][s]
__device__ float g_fcp[KSPLIT * H * B];   // fc partials [ks][h][b]

// Grid-wide sense-reversing barrier (single atomic counter — measured faster
// than distributed flag polling (R7) and ticket stealing (R9)).
__device__ int          g_bar_count = 0;
__device__ volatile int g_bar_sense = 0;

__device__ __forceinline__ void grid_barrier(int& ls) {
    __syncthreads();
    if (threadIdx.x == 0) {
        const int target = ls ^ 1;
        ls = target;
        __threadfence();
        if (atomicAdd(&g_bar_count, 1) == NBLK - 1) {
            atomicExch(&g_bar_count, 0);
            __threadfence();
            g_bar_sense = target;
        } else {
            while (g_bar_sense != target) { }
        }
        __threadfence();
    } else {
        ls ^= 1;
    }
    __syncthreads();
}

__device__ __forceinline__ void f4add(float4& a, const float4 v) {
    a.x += v.x; a.y += v.y; a.z += v.z; a.w += v.w;
}

// Streaming load for PURE INPUTS with zero reuse (phase-1 x only — R11 showed
// blanket no_allocate elsewhere regresses): L1 bypass + 256B L2 prefetch.
__device__ __forceinline__ float4 ldg_stream(const float4* p) {
    float4 v;
    asm volatile("ld.global.nc.L1::no_allocate.L2::256B.v4.f32 {%0,%1,%2,%3}, [%4];"
                 : "=f"(v.x), "=f"(v.y), "=f"(v.z), "=f"(v.w)
                 : "l"(p));
    return v;
}

__global__ void __launch_bounds__(NTHR, 2)
ham_persistent(const float* __restrict__ x,
               const float* __restrict__ W_t,
               const float* __restrict__ b_t,
               const float* __restrict__ gamma,
               const float* __restrict__ beta,
               const float* __restrict__ W_l,
               const float* __restrict__ b_l,
               const float* __restrict__ G_h,
               float* __restrict__ out_score,
               float* __restrict__ out_fc,
               float* __restrict__ out_omega) {
    __shared__ __align__(16) float sm[4352];   // 17.4 KB, reused per phase

    const int blk = blockIdx.x;
    const int tid = threadIdx.x;
    int ls = g_bar_sense;                      // replay-safe sense init

    // ---------------- Phase 1: x-sum partials ------------------------------
    // block = (cq, b), 256 threads = 4 c-subgroups (32 rows) x 64 s-columns;
    // 2 rows/iter into 6 independent chains (deep MLP now that L1 bypass
    // removed the old bottleneck; R8's negative result was confounded).
    {
        const int cq  = blk >> 6;              // 0..3
        const int b   = blk & 63;
        const int cs  = tid >> 6;              // 0..3
        const int s64 = tid & 63;

        const float4* p = reinterpret_cast<const float4*>(x)
                        + ((size_t)b * C + cq * 128 + cs * 32) * (S / 4);
        float4 a0 = make_float4(0.f, 0.f, 0.f, 0.f);
        float4 a1 = a0, a2 = a0, a3 = a0, a4 = a0, a5 = a0;
#pragma unroll 8
        for (int c = 0; c < 32; c += 2) {
            const float4* r0 = p + c * (S / 4);
            const float4* r1 = r0 + (S / 4);
            f4add(a0, ldg_stream(r0 + s64));
            f4add(a1, ldg_stream(r0 + s64 + 64));
            f4add(a2, ldg_stream(r0 + s64 + 128));
            f4add(a3, ldg_stream(r1 + s64));
            f4add(a4, ldg_stream(r1 + s64 + 64));
            f4add(a5, ldg_stream(r1 + s64 + 128));
        }
        f4add(a0, a3); f4add(a1, a4); f4add(a2, a5);
        float4* sm4 = reinterpret_cast<float4*>(sm);   // [4][192]
        sm4[cs * 192 + s64]       = a0;
        sm4[cs * 192 + s64 + 64]  = a1;
        sm4[cs * 192 + s64 + 128] = a2;
        __syncthreads();
        if (tid < 192) {
            float4 r = sm4[tid];
            f4add(r, sm4[192 + tid]);
            f4add(r, sm4[384 + tid]);
            f4add(r, sm4[576 + tid]);
            reinterpret_cast<float4*>(g_xmp)[(cq * B + b) * (S / 4) + tid] = r;
        }
    }
    grid_barrier(ls);

    // ---------------- Phase 2: fc partial GEMM -----------------------------
    // fc[b,h] = sum_s x_mean[b,s] * (W_t[h,s] + 4*W_t[h,s+S]); x_mean built
    // on the fly from the 4 c-quarter partials (L2-resident).
    // 256 blocks = 16 h-tiles x 16 s-splits of 48; 4x4 register tile.
    {
        float (*Xs)[64] = reinterpret_cast<float(*)[64]>(sm);          // [sk][b]
        float (*Ws)[64] = reinterpret_cast<float(*)[64]>(sm + 1024);   // [sk][h]
        const int h0 = (blk >> 4) * 64;
        const int s0 = (blk & 15) * SCHUNK;
        const int tx = tid & 15;          // b group
        const int ty = tid >> 4;          // h group

        float acc[4][4] = {};             // [h][b]
        for (int sc = 0; sc < SCHUNK; sc += 16) {
            for (int i = tid; i < 1024; i += NTHR) {
                int hh = i >> 4, sk = i & 15;
                int s = s0 + sc + sk;
                const float* wr = W_t + (size_t)(h0 + hh) * (2 * S);
                Ws[sk][hh] = wr[s] + 4.0f * wr[s + S];
            }
            for (int i = tid; i < 1024; i += NTHR) {
                int bb = i >> 4, sk = i & 15;
                int idx = bb * S + s0 + sc + sk;
                float v = g_xmp[idx] + g_xmp[B * S + idx]
                        + g_xmp[2 * B * S + idx] + g_xmp[3 * B * S + idx];
                Xs[sk][bb] = v * (1.0f / C);
            }
            __syncthreads();
#pragma unroll
            for (int sk = 0; sk < 16; ++sk) {
                float a_[4], w_[4];
#pragma unroll
                for (int i = 0; i < 4; ++i) a_[i] = Ws[sk][ty * 4 + i];
#pragma unroll
                for (int j = 0; j < 4; ++j) w_[j] = Xs[sk][tx * 4 + j];
#pragma unroll
                for (int i = 0; i < 4; ++i)
#pragma unroll
                    for (int j = 0; j < 4; ++j)
                        acc[i][j] += a_[i] * w_[j];
            }
            __syncthreads();
        }
        float* dst = g_fcp + (size_t)(blk & 15) * (H * B);
#pragma unroll
        for (int i = 0; i < 4; ++i) {
            float4 v = make_float4(acc[i][0], acc[i][1], acc[i][2], acc[i][3]);
            *reinterpret_cast<float4*>(&dst[(h0 + ty * 4 + i) * B + tx * 4]) = v;
        }
    }
    grid_barrier(ls);

    // ---------------- Phase 3: BN (biased var over batch) + ReLU -----------
    // block handles 4 h columns x all 64 b; writes out_fc [b][h].
    {
        const int b    = tid & 63;
        const int hl   = tid >> 6;
        const int h    = blk * 4 + hl;
        const int wid  = tid >> 5;
        const int lane = tid & 31;

        float v = b_t[h];
#pragma unroll
        for (int ks = 0; ks < KSPLIT; ++ks)
            v += g_fcp[(size_t)ks * (H * B) + h * B + b];

        float s = v;
#pragma unroll
        for (int o = 16; o; o >>= 1) s += __shfl_down_sync(0xffffffffu, s, o);
        if (!lane) sm[wid] = s;
        __syncthreads();
        const float mean = (sm[hl * 2] + sm[hl * 2 + 1]) * (1.0f / B);

        const float d = v - mean;
        float s2 = d * d;
#pragma unroll
        for (int o = 16; o; o >>= 1) s2 += __shfl_down_sync(0xffffffffu, s2, o);
        if (!lane) sm[8 + wid] = s2;
        __syncthreads();
        const float var = (sm[8 + hl * 2] + sm[8 + hl * 2 + 1]) * (1.0f / B);

        out_fc[b * H + h] =
            fmaxf(d * rsqrtf(var + 1e-5f) * gamma[h] + beta[h], 0.0f);
    }
    grid_barrier(ls);

    // ---------------- Phase 4: score = sigmoid(relu_fc @ W_l^T + b_l) ------
    // block = (b-quad, k-octet): 16 x 16 = 256 blocks. W_l rows reused by 4 b.
    {
        const int b0 = (blk >> 4) * 4;
        const int k0 = (blk & 15) * 8;
        float4* r4 = reinterpret_cast<float4*>(sm);     // [4][256] float4

        for (int i = tid; i < 4 * (H / 4); i += NTHR)
            r4[i] = reinterpret_cast<const float4*>(out_fc)
                        [(b0 + (i >> 8)) * (H / 4) + (i & 255)];
        __syncthreads();

        const int w = tid >> 5, lane = tid & 31;
        const int k = k0 + w;
        const float4* wl4 = reinterpret_cast<const float4*>(W_l + (size_t)k * H);
        float acc0 = 0.f, acc1 = 0.f, acc2 = 0.f, acc3 = 0.f;
#pragma unroll
        for (int j = 0; j < 8; ++j) {
            const float4 wv = __ldg(wl4 + lane + 32 * j);
            const float4 a0 = r4[0 * 256 + lane + 32 * j];
            const float4 a1 = r4[1 * 256 + lane + 32 * j];
            const float4 a2 = r4[2 * 256 + lane + 32 * j];
            const float4 a3 = r4[3 * 256 + lane + 32 * j];
            acc0 += a0.x * wv.x + a0.y * wv.y + a0.z * wv.z + a0.w * wv.w;
            acc1 += a1.x * wv.x + a1.y * wv.y + a1.z * wv.z + a1.w * wv.w;
            acc2 += a2.x * wv.x + a2.y * wv.y + a2.z * wv.z + a2.w * wv.w;
            acc3 += a3.x * wv.x + a3.y * wv.y + a3.z * wv.z + a3.w * wv.w;
        }
#pragma unroll
        for (int o = 16; o; o >>= 1) {
            acc0 += __shfl_down_sync(0xffffffffu, acc0, o);
            acc1 += __shfl_down_sync(0xffffffffu, acc1, o);
            acc2 += __shfl_down_sync(0xffffffffu, acc2, o);
            acc3 += __shfl_down_sync(0xffffffffu, acc3, o);
        }
        if (!lane) {
            const float bl = b_l[k];
            out_score[(b0 + 0) * K + k] = 1.0f / (1.0f + expf(-(acc0 + bl)));
            out_score[(b0 + 1) * K + k] = 1.0f / (1.0f + expf(-(acc1 + bl)));
            out_score[(b0 + 2) * K + k] = 1.0f / (1.0f + expf(-(acc2 + bl)));
            out_score[(b0 + 3) * K + k] = 1.0f / (1.0f + expf(-(acc3 + bl)));
        }
    }
    grid_barrier(ls);

    // ---------------- Phase 5: Q = score @ G_h, omega broadcast ------------
    // block = (b, n-slice of 64): 64 x 4 = 256 blocks.
    {
        const int b  = blk >> 2;
        const int n0 = (blk & 3) * 64;
        float* scsh  = sm;          // [128] score
        float* qpart = sm + 128;    // [4][64]
        float* qv    = sm + 384;    // [64]

        if (tid < K) scsh[tid] = out_score[b * K + tid];  // plain load (ours)
        __syncthreads();

        const int kh = tid >> 6;    // 0..3 -> k range [kh*32, kh*32+32)
        const int n  = tid & 63;
        float acc = 0.f;
#pragma unroll 8
        for (int j = 0; j < 32; ++j) {
            const int k = kh * 32 + j;
            acc += scsh[k] * __ldg(G_h + k * KN + n0 + n);
        }
        qpart[kh * 64 + n] = acc;
        __syncthreads();
        if (tid < 64)
            qv[tid] = qpart[tid] + qpart[64 + tid]
                    + qpart[128 + tid] + qpart[192 + tid];
        __syncthreads();

        // write 64 n rows x 200 a = 3200 float4
        float4* po = reinterpret_cast<float4*>(
            out_omega + (size_t)b * KN * A + (size_t)n0 * A);
#pragma unroll
        for (int it = 0; it < 13; ++it) {
            const int i4 = it * NTHR + tid;
            if (i4 < 64 * (A / 4)) {
                const float v = qv[i4 / (A / 4)];
                po[i4] = make_float4(v, v, v, v);
            }
        }
    }
}

// ---------------------------------------------------------------------------
extern "C" void kernel_launch(void* const* d_in, const int* in_sizes, int n_in,
                              void* d_out, int out_size) {
    const float* x     = (const float*)d_in[0];
    // d_in[1] omega_h, d_in[2] W_s1, d_in[3] W_s2: mathematically dead
    const float* W_t   = (const float*)d_in[4];
    const float* b_t   = (const float*)d_in[5];
    const float* gamma = (const float*)d_in[6];
    const float* beta  = (const float*)d_in[7];
    const float* W_l   = (const float*)d_in[8];
    const float* b_l   = (const float*)d_in[9];
    const float* G_h   = (const float*)d_in[10];

    float* out       = (float*)d_out;
    float* out_score = out;                    // [B, K]
    float* out_fc    = out + B * K;            // [B, H]
    float* out_omega = out + B * K + B * H;    // [B, KN, A]

    ham_persistent<<<NBLK, NTHR>>>(x, W_t, b_t, gamma, beta, W_l, b_l, G_h,
                                   out_score, out_fc, out_omega);
}